// round 2
// baseline (speedup 1.0000x reference)
#include <cuda_runtime.h>
#include <cuda_bf16.h>
#include <cstdint>
#include <cstddef>

#define T_STEPS 2048
#define BATCH   64
#define HID     256
#define INDIM   128
#define GJ      8      // j-blocks (32 hidden units each)
#define GB      16     // batch-blocks (4 batches each)

// ---- scratch (device globals: allocation-free rule) ----
__device__ __align__(16) float g_gated[(size_t)BATCH * T_STEPS * INDIM];       // 64 MB
__device__ __align__(16) float g_xpart[(size_t)T_STEPS * BATCH * 4 * HID];     // 512 MB
__device__ __align__(16) float g_h[2][BATCH * HID];
__device__ unsigned g_cnt16[GB];
__device__ unsigned g_epoch16[GB];

// ---------- helpers ----------
__device__ __forceinline__ float sigm(float x) {
    return __fdividef(1.f, 1.f + __expf(-x));
}
__device__ __forceinline__ void ffma2(unsigned long long& d, unsigned long long a,
                                      unsigned long long b) {
    asm("fma.rn.f32x2 %0, %1, %2, %0;" : "+l"(d) : "l"(a), "l"(b));
}
__device__ __forceinline__ unsigned long long dup2(float x) {
    unsigned long long r;
    asm("mov.b64 %0, {%1, %1};" : "=l"(r) : "f"(x));
    return r;
}
__device__ __forceinline__ void unpack2(unsigned long long v, float& x, float& y) {
    asm("mov.b64 {%0, %1}, %2;" : "=f"(x), "=f"(y) : "l"(v));
}

// ---------- kernel 1: gated = xd * sigmoid(w) ----------
__global__ void __launch_bounds__(256) k_gate(const float* __restrict__ xd,
                                              const float* __restrict__ w) {
    size_t i = ((size_t)blockIdx.x * 256 + threadIdx.x) * 4;
    float4 x = __ldg((const float4*)(xd + i));
    float4 g = __ldg((const float4*)(w + i));
    float4 o;
    o.x = x.x * sigm(g.x);
    o.y = x.y * sigm(g.y);
    o.z = x.z * sigm(g.z);
    o.w = x.w * sigm(g.w);
    *(float4*)(g_gated + i) = o;
}

// ---------- kernel 2: x_part[t][b][col] = gated[b][t][:] @ W_ih^T + (b_ih+b_hh) ----------
// CTA tile: 128 M x 64 N, K=128 staged in 4 chunks of 32. f32x2 FFMA.
__global__ void __launch_bounds__(256, 2) k_xpart(const float* __restrict__ Wih,
                                                  const float* __restrict__ bih,
                                                  const float* __restrict__ bhh) {
    __shared__ float As[32 * 132];   // [k][m] padded
    __shared__ float Bs[32 * 72];    // [k][n] padded (72: 16B-aligned rows)

    const int tid = threadIdx.x;
    const int tx = tid & 15;         // n quad (4 n each)
    const int ty = tid >> 4;         // m group (8 m each)
    const int m_base = blockIdx.y * 128;
    const int n_base = blockIdx.x * 64;

    unsigned long long acc[8][2];
#pragma unroll
    for (int i = 0; i < 8; ++i) { acc[i][0] = 0ull; acc[i][1] = 0ull; }

    const int am = tid & 127, ah = (tid >> 7) * 16;   // A stage: m row, k half
    const int bn = tid & 63,  bh = (tid >> 6) * 8;    // B stage: n row, k quarter
    const float* Ag = g_gated + (size_t)(m_base + am) * INDIM;
    const float* Bg = Wih + (size_t)(n_base + bn) * INDIM;

    for (int ks = 0; ks < 4; ++ks) {
        const int k0 = ks * 32;
#pragma unroll
        for (int u = 0; u < 4; ++u) {
            float4 v = __ldg((const float4*)(Ag + k0 + ah + u * 4));
            int k = ah + u * 4;
            As[(k + 0) * 132 + am] = v.x;
            As[(k + 1) * 132 + am] = v.y;
            As[(k + 2) * 132 + am] = v.z;
            As[(k + 3) * 132 + am] = v.w;
        }
#pragma unroll
        for (int u = 0; u < 2; ++u) {
            float4 v = __ldg((const float4*)(Bg + k0 + bh + u * 4));
            int k = bh + u * 4;
            Bs[(k + 0) * 72 + bn] = v.x;
            Bs[(k + 1) * 72 + bn] = v.y;
            Bs[(k + 2) * 72 + bn] = v.z;
            Bs[(k + 3) * 72 + bn] = v.w;
        }
        __syncthreads();
#pragma unroll
        for (int k = 0; k < 32; ++k) {
            const ulonglong2 bb = *(const ulonglong2*)&Bs[k * 72 + tx * 4];
            const float4 a0 = *(const float4*)&As[k * 132 + ty * 8];
            const float4 a1 = *(const float4*)&As[k * 132 + ty * 8 + 4];
            float a[8] = {a0.x, a0.y, a0.z, a0.w, a1.x, a1.y, a1.z, a1.w};
#pragma unroll
            for (int i = 0; i < 8; ++i) {
                unsigned long long d = dup2(a[i]);
                ffma2(acc[i][0], d, bb.x);
                ffma2(acc[i][1], d, bb.y);
            }
        }
        __syncthreads();
    }

    const int col0 = n_base + tx * 4;
    float4 bias;
    bias.x = __ldg(bih + col0 + 0) + __ldg(bhh + col0 + 0);
    bias.y = __ldg(bih + col0 + 1) + __ldg(bhh + col0 + 1);
    bias.z = __ldg(bih + col0 + 2) + __ldg(bhh + col0 + 2);
    bias.w = __ldg(bih + col0 + 3) + __ldg(bhh + col0 + 3);
#pragma unroll
    for (int i = 0; i < 8; ++i) {
        int gm = m_base + ty * 8 + i;
        int b = gm >> 11;              // m = b*2048 + t
        int t = gm & 2047;
        float x0, x1, x2, x3;
        unpack2(acc[i][0], x0, x1);
        unpack2(acc[i][1], x2, x3);
        float4 o = make_float4(x0 + bias.x, x1 + bias.y, x2 + bias.z, x3 + bias.w);
        *(float4*)&g_xpart[((size_t)t * BATCH + b) * (4 * HID) + col0] = o;
    }
}

// ---------- kernel 3: persistent LSTM recurrence ----------
// 128 CTAs: jb = blockIdx&7 (32 hidden units), bb = blockIdx>>3 (4 batches).
// Thread (rg = tid>>3 in [0,32): local j; kc = tid&7: k-slice).
// Per thread: W_hh[g*256 + jb*32 + rg][k] for k = 4*kc + 32*m + r (m<8, r<4),
// held as k-pair f32x2 operands: w2[g][2m]=(k r0,r1), w2[g][2m+1]=(r2,r3).
__global__ void __launch_bounds__(256, 1) k_rec(const float* __restrict__ Whh) {
    const int jb = blockIdx.x & 7;
    const int bb = blockIdx.x >> 3;
    const int tid = threadIdx.x;
    const int kc = tid & 7;
    const int rg = tid >> 3;

    __shared__ float sh_h[4 * HID];      // [b][k]
    __shared__ float xp_s[4 * 4 * 32];   // [b][g][j]

    // persistent W_hh registers (64 ull = 128 regs)
    unsigned long long w2[4][16];
#pragma unroll
    for (int g = 0; g < 4; ++g) {
        const float* rp = Whh + (size_t)(g * HID + jb * 32 + rg) * HID + 4 * kc;
#pragma unroll
        for (int m = 0; m < 8; ++m) {
            ulonglong2 v = *(const ulonglong2*)(rp + 32 * m);
            w2[g][2 * m]     = v.x;
            w2[g][2 * m + 1] = v.y;
        }
    }

    const unsigned e0 = *(volatile unsigned*)&g_epoch16[bb];

    // init h0 = 0 (each CTA covers its own (b,j) cells), c = 0 in register
    float c = 0.f;
    if ((tid & 7) < 4) {
        int b = tid & 3;  // == kc here
        g_h[0][(bb * 4 + b) * HID + jb * 32 + rg] = 0.f;
    }
    // ---- group barrier #1 ----
    {
        __syncthreads();
        if (tid == 0) {
            __threadfence();
            unsigned old = atomicAdd(&g_cnt16[bb], 1u);
            if (old == GJ - 1) {
                atomicExch(&g_cnt16[bb], 0u);
                __threadfence();
                atomicAdd(&g_epoch16[bb], 1u);
            } else {
                while (*(volatile unsigned*)&g_epoch16[bb] - e0 < 1u) {}
                __threadfence();
            }
        }
        __syncthreads();
    }

    for (int t = 0; t < T_STEPS; ++t) {
        const int cur = t & 1, nxt = cur ^ 1;

        // load h (L2, ping-pong) into shared [b][k]
        {
            const int b = tid >> 6, k4 = (tid & 63) * 4;
            float4 h4 = __ldcg((const float4*)&g_h[cur][(bb * 4 + b) * HID + k4]);
            *(float4*)&sh_h[b * HID + k4] = h4;
        }
        // load x_part slice into shared [b][g][j]
        if (tid < 128) {
            const int chunk = tid >> 3;           // b*4+g
            const int b = chunk >> 2, g = chunk & 3;
            const int off = (tid & 7) * 4;
            float4 xp4 = __ldg((const float4*)&g_xpart[((size_t)t * BATCH + bb * 4 + b) * (4 * HID)
                                                        + g * HID + jb * 32 + off]);
            *(float4*)&xp_s[chunk * 32 + off] = xp4;
        }
        __syncthreads();

        // z_hh partials: acc[g][b] holds k-pair packed sums
        unsigned long long acc[4][4];
#pragma unroll
        for (int g = 0; g < 4; ++g)
#pragma unroll
            for (int b = 0; b < 4; ++b) acc[g][b] = 0ull;

#pragma unroll
        for (int m = 0; m < 8; ++m) {
#pragma unroll
            for (int b = 0; b < 4; ++b) {
                ulonglong2 h4 = *(const ulonglong2*)&sh_h[b * HID + 32 * m + 4 * kc];
#pragma unroll
                for (int g = 0; g < 4; ++g) {
                    ffma2(acc[g][b], w2[g][2 * m],     h4.x);
                    ffma2(acc[g][b], w2[g][2 * m + 1], h4.y);
                }
            }
        }

        // horizontal (k-pair) + cross-kc shuffle reduction
        float z[4][4];
#pragma unroll
        for (int g = 0; g < 4; ++g)
#pragma unroll
            for (int b = 0; b < 4; ++b) {
                float lo, hi;
                unpack2(acc[g][b], lo, hi);
                float s = lo + hi;
                s += __shfl_xor_sync(0xffffffffu, s, 1);
                s += __shfl_xor_sync(0xffffffffu, s, 2);
                s += __shfl_xor_sync(0xffffffffu, s, 4);
                z[g][b] = s;
            }

        // cell update: lane kc<4 owns batch b=kc, hidden j=rg
        if (kc < 4) {
            const int b = kc;
            float zi = z[0][b] + xp_s[(b * 4 + 0) * 32 + rg];
            float zf = z[1][b] + xp_s[(b * 4 + 1) * 32 + rg];
            float zg = z[2][b] + xp_s[(b * 4 + 2) * 32 + rg];
            float zo = z[3][b] + xp_s[(b * 4 + 3) * 32 + rg];
            c = sigm(zf) * c + sigm(zi) * tanhf(zg);
            float h = sigm(zo) * tanhf(c);
            g_h[nxt][(bb * 4 + b) * HID + jb * 32 + rg] = h;
        }

        // ---- group barrier (target t+2) ----
        __syncthreads();
        if (tid == 0) {
            __threadfence();
            unsigned old = atomicAdd(&g_cnt16[bb], 1u);
            if (old == GJ - 1) {
                atomicExch(&g_cnt16[bb], 0u);
                __threadfence();
                atomicAdd(&g_epoch16[bb], 1u);
            } else {
                unsigned target = (unsigned)(t + 2);
                while (*(volatile unsigned*)&g_epoch16[bb] - e0 < target) {}
                __threadfence();
            }
        }
        __syncthreads();
    }
    // final h in g_h[0] (t=2047 writes nxt=0)
}

// ---------- kernel 4: out[b] = h_T[b] @ W_out^T + b_out ----------
__global__ void __launch_bounds__(256) k_out(const float* __restrict__ Wout,
                                             const float* __restrict__ bout,
                                             float* __restrict__ out) {
    const int b = blockIdx.x;
    const int tid = threadIdx.x;
    float v = g_h[0][b * HID + tid] * __ldg(Wout + tid);
#pragma unroll
    for (int d = 16; d >= 1; d >>= 1) v += __shfl_xor_sync(0xffffffffu, v, d);
    __shared__ float s[8];
    if ((tid & 31) == 0) s[tid >> 5] = v;
    __syncthreads();
    if (tid == 0) {
        float acc = 0.f;
#pragma unroll
        for (int i = 0; i < 8; ++i) acc += s[i];
        out[b] = acc + __ldg(bout);
    }
}

// ---------- launch ----------
extern "C" void kernel_launch(void* const* d_in, const int* in_sizes, int n_in,
                              void* d_out, int out_size) {
    const float* xd   = (const float*)d_in[0];
    const float* w    = (const float*)d_in[1];
    const float* Wih  = (const float*)d_in[2];
    const float* bih  = (const float*)d_in[3];
    const float* Whh  = (const float*)d_in[4];
    const float* bhh  = (const float*)d_in[5];
    const float* Wout = (const float*)d_in[6];
    const float* bout = (const float*)d_in[7];
    float* out = (float*)d_out;

    // 1) gated = xd * sigmoid(w): 16.8M elems, 4 per thread
    k_gate<<<(BATCH * T_STEPS * INDIM) / (256 * 4), 256>>>(xd, w);

    // 2) x_part GEMM: M=131072 (b*T+t), N=1024, K=128
    dim3 gx(1024 / 64, (BATCH * T_STEPS) / 128);
    k_xpart<<<gx, 256>>>(Wih, bih, bhh);

    // 3) persistent recurrence: 128 CTAs (co-resident on 148 SMs)
    k_rec<<<GJ * GB, 256>>>(Whh);

    // 4) output projection
    k_out<<<BATCH, 256>>>(Wout, bout, out);
}

// round 3
// speedup vs baseline: 1.0805x; 1.0805x over previous
#include <cuda_runtime.h>
#include <cuda_bf16.h>
#include <cstdint>
#include <cstddef>

#define T_STEPS 2048
#define BATCH   64
#define HID     256
#define INDIM   128
#define GJ      8      // j-slices per cluster (32 hidden units each)
#define GB      16     // batch-blocks (4 batches each)

// ---- scratch (device globals: allocation-free rule) ----
__device__ __align__(16) float g_gated[(size_t)BATCH * T_STEPS * INDIM];       // 64 MB
__device__ __align__(16) float g_xpart[(size_t)T_STEPS * BATCH * 4 * HID];     // 512 MB
__device__ __align__(16) float g_hT[BATCH * HID];

// ---------- helpers ----------
__device__ __forceinline__ float sigm(float x) {
    return __fdividef(1.f, 1.f + __expf(-x));
}
__device__ __forceinline__ void ffma2(unsigned long long& d, unsigned long long a,
                                      unsigned long long b) {
    asm("fma.rn.f32x2 %0, %1, %2, %0;" : "+l"(d) : "l"(a), "l"(b));
}
__device__ __forceinline__ unsigned long long dup2(float x) {
    unsigned long long r;
    asm("mov.b64 %0, {%1, %1};" : "=l"(r) : "f"(x));
    return r;
}
__device__ __forceinline__ void unpack2(unsigned long long v, float& x, float& y) {
    asm("mov.b64 {%0, %1}, %2;" : "=f"(x), "=f"(y) : "l"(v));
}
__device__ __forceinline__ unsigned smem_u32(const void* p) {
    return (unsigned)__cvta_generic_to_shared(p);
}
__device__ __forceinline__ unsigned mapa_rank(unsigned local_addr, int rank) {
    unsigned r;
    asm("mapa.shared::cluster.u32 %0, %1, %2;" : "=r"(r) : "r"(local_addr), "r"(rank));
    return r;
}
__device__ __forceinline__ void st_cluster_f32(unsigned addr, float v) {
    asm volatile("st.shared::cluster.f32 [%0], %1;" :: "r"(addr), "f"(v) : "memory");
}
#define CLUSTER_ARRIVE() asm volatile("barrier.cluster.arrive.aligned;" ::: "memory")
#define CLUSTER_WAIT()   asm volatile("barrier.cluster.wait.aligned;"   ::: "memory")

// ---------- kernel 1: gated = xd * sigmoid(w) ----------
__global__ void __launch_bounds__(256) k_gate(const float* __restrict__ xd,
                                              const float* __restrict__ w) {
    size_t i = ((size_t)blockIdx.x * 256 + threadIdx.x) * 4;
    float4 x = __ldg((const float4*)(xd + i));
    float4 g = __ldg((const float4*)(w + i));
    float4 o;
    o.x = x.x * sigm(g.x);
    o.y = x.y * sigm(g.y);
    o.z = x.z * sigm(g.z);
    o.w = x.w * sigm(g.w);
    *(float4*)(g_gated + i) = o;
}

// ---------- kernel 2: x_part[t][b][col] = gated[b][t][:] @ W_ih^T + (b_ih+b_hh) ----------
__global__ void __launch_bounds__(256, 2) k_xpart(const float* __restrict__ Wih,
                                                  const float* __restrict__ bih,
                                                  const float* __restrict__ bhh) {
    __shared__ float As[32 * 132];   // [k][m] padded
    __shared__ float Bs[32 * 72];    // [k][n] padded

    const int tid = threadIdx.x;
    const int tx = tid & 15;
    const int ty = tid >> 4;
    const int m_base = blockIdx.y * 128;
    const int n_base = blockIdx.x * 64;

    unsigned long long acc[8][2];
#pragma unroll
    for (int i = 0; i < 8; ++i) { acc[i][0] = 0ull; acc[i][1] = 0ull; }

    const int am = tid & 127, ah = (tid >> 7) * 16;
    const int bn = tid & 63,  bh = (tid >> 6) * 8;
    const float* Ag = g_gated + (size_t)(m_base + am) * INDIM;
    const float* Bg = Wih + (size_t)(n_base + bn) * INDIM;

    for (int ks = 0; ks < 4; ++ks) {
        const int k0 = ks * 32;
#pragma unroll
        for (int u = 0; u < 4; ++u) {
            float4 v = __ldg((const float4*)(Ag + k0 + ah + u * 4));
            int k = ah + u * 4;
            As[(k + 0) * 132 + am] = v.x;
            As[(k + 1) * 132 + am] = v.y;
            As[(k + 2) * 132 + am] = v.z;
            As[(k + 3) * 132 + am] = v.w;
        }
#pragma unroll
        for (int u = 0; u < 2; ++u) {
            float4 v = __ldg((const float4*)(Bg + k0 + bh + u * 4));
            int k = bh + u * 4;
            Bs[(k + 0) * 72 + bn] = v.x;
            Bs[(k + 1) * 72 + bn] = v.y;
            Bs[(k + 2) * 72 + bn] = v.z;
            Bs[(k + 3) * 72 + bn] = v.w;
        }
        __syncthreads();
#pragma unroll
        for (int k = 0; k < 32; ++k) {
            const ulonglong2 bb = *(const ulonglong2*)&Bs[k * 72 + tx * 4];
            const float4 a0 = *(const float4*)&As[k * 132 + ty * 8];
            const float4 a1 = *(const float4*)&As[k * 132 + ty * 8 + 4];
            float a[8] = {a0.x, a0.y, a0.z, a0.w, a1.x, a1.y, a1.z, a1.w};
#pragma unroll
            for (int i = 0; i < 8; ++i) {
                unsigned long long d = dup2(a[i]);
                ffma2(acc[i][0], d, bb.x);
                ffma2(acc[i][1], d, bb.y);
            }
        }
        __syncthreads();
    }

    const int col0 = n_base + tx * 4;
    float4 bias;
    bias.x = __ldg(bih + col0 + 0) + __ldg(bhh + col0 + 0);
    bias.y = __ldg(bih + col0 + 1) + __ldg(bhh + col0 + 1);
    bias.z = __ldg(bih + col0 + 2) + __ldg(bhh + col0 + 2);
    bias.w = __ldg(bih + col0 + 3) + __ldg(bhh + col0 + 3);
#pragma unroll
    for (int i = 0; i < 8; ++i) {
        int gm = m_base + ty * 8 + i;
        int b = gm >> 11;              // m = b*2048 + t
        int t = gm & 2047;
        float x0, x1, x2, x3;
        unpack2(acc[i][0], x0, x1);
        unpack2(acc[i][1], x2, x3);
        float4 o = make_float4(x0 + bias.x, x1 + bias.y, x2 + bias.z, x3 + bias.w);
        *(float4*)&g_xpart[((size_t)t * BATCH + b) * (4 * HID) + col0] = o;
    }
}

// ---------- kernel 3: persistent LSTM recurrence (cluster of 8 j-slices) ----------
// grid = 128 CTAs, cluster_dims(8): rank jb in [0,8) = j-slice, bb = blockIdx>>3.
// Thread: rg = tid>>3 (local j), kc = tid&7 (k-slice).
// W_hh[g*256 + jb*32 + rg][4*kc + 32*m + r] held as f32x2 pairs in registers.
// h lives in cluster-replicated smem ping-pong buffers, exchanged via DSMEM.
__global__ void __launch_bounds__(256, 1) __cluster_dims__(GJ, 1, 1)
k_rec(const float* __restrict__ Whh) {
    const int tid = threadIdx.x;
    const int kc = tid & 7;
    const int rg = tid >> 3;
    unsigned jb;
    asm("mov.u32 %0, %%cluster_ctarank;" : "=r"(jb));
    const int bb = blockIdx.x >> 3;

    __shared__ __align__(16) float buf[2][4 * HID];   // h ping-pong: [p][b][k]
    __shared__ __align__(16) float xp_s[16 * 32];     // [b*4+g][j]

    // persistent W_hh registers (64 ull = 128 regs)
    unsigned long long w2[4][16];
#pragma unroll
    for (int g = 0; g < 4; ++g) {
        const float* rp = Whh + (size_t)(g * HID + jb * 32 + rg) * HID + 4 * kc;
#pragma unroll
        for (int m = 0; m < 8; ++m) {
            ulonglong2 v = *(const ulonglong2*)(rp + 32 * m);
            w2[g][2 * m]     = v.x;
            w2[g][2 * m + 1] = v.y;
        }
    }

    // zero h(0) buffer (local copy; every CTA zeroes its own)
    *(float4*)&buf[0][tid * 4] = make_float4(0.f, 0.f, 0.f, 0.f);

    // owner lanes: kc<4 owns cell (b = kc, j = jb*32 + rg)
    const int ob = kc;                       // owner batch (valid when kc<4)
    const unsigned cell_off = (unsigned)(ob * HID + jb * 32 + rg) * 4u;
    unsigned rcell[GJ];
    {
        unsigned my0 = smem_u32(&buf[0][0]) + cell_off;
#pragma unroll
        for (int r = 0; r < GJ; ++r) rcell[r] = mapa_rank(my0, r);
    }

    // prefetch xp(t=0): lanes < 128, chunk = b*4+g
    const int chunk = tid >> 3, xb = chunk >> 2, xg = chunk & 3, xoff = (tid & 7) * 4;
    const float* xp_base = g_xpart + ((size_t)bb * 4) * (4 * HID) + xg * HID + jb * 32 + xoff
                         + (size_t)xb * (4 * HID);
    float4 xp_pf = make_float4(0.f, 0.f, 0.f, 0.f);
    if (tid < 128) xp_pf = __ldg((const float4*)(xp_base));

    float c = 0.f;
    CLUSTER_ARRIVE();
    CLUSTER_WAIT();

    int p = 0;
    for (int t = 0; t < T_STEPS; ++t) {
        // ---- z_hh partial GEMM over local h buffer ----
        unsigned long long acc[4][4];
#pragma unroll
        for (int g = 0; g < 4; ++g)
#pragma unroll
            for (int b = 0; b < 4; ++b) acc[g][b] = 0ull;

        const float* hb = &buf[p][0];
#pragma unroll
        for (int m = 0; m < 8; ++m) {
#pragma unroll
            for (int b = 0; b < 4; ++b) {
                ulonglong2 h4 = *(const ulonglong2*)&hb[b * HID + 32 * m + 4 * kc];
#pragma unroll
                for (int g = 0; g < 4; ++g) {
                    ffma2(acc[g][b], w2[g][2 * m],     h4.x);
                    ffma2(acc[g][b], w2[g][2 * m + 1], h4.y);
                }
            }
        }

        // ---- horizontal + cross-kc reduction ----
        float z[4][4];
#pragma unroll
        for (int g = 0; g < 4; ++g)
#pragma unroll
            for (int b = 0; b < 4; ++b) {
                float lo, hi;
                unpack2(acc[g][b], lo, hi);
                float s = lo + hi;
                s += __shfl_xor_sync(0xffffffffu, s, 1);
                s += __shfl_xor_sync(0xffffffffu, s, 2);
                s += __shfl_xor_sync(0xffffffffu, s, 4);
                z[g][b] = s;
            }

        // ---- stage prefetched xp into smem ----
        if (tid < 128) *(float4*)&xp_s[chunk * 32 + xoff] = xp_pf;
        __syncthreads();

        // ---- cell update (owners) + DSMEM broadcast of h(t+1) ----
        if (kc < 4) {
            const int b = kc;
            float zi = z[0][b] + xp_s[(b * 4 + 0) * 32 + rg];
            float zf = z[1][b] + xp_s[(b * 4 + 1) * 32 + rg];
            float zg = z[2][b] + xp_s[(b * 4 + 2) * 32 + rg];
            float zo = z[3][b] + xp_s[(b * 4 + 3) * 32 + rg];
            c = sigm(zf) * c + sigm(zi) * tanhf(zg);
            float h = sigm(zo) * tanhf(c);
            const unsigned boff = (unsigned)((p ^ 1) * (4 * HID) * 4);
#pragma unroll
            for (int r = 0; r < GJ; ++r) st_cluster_f32(rcell[r] + boff, h);
            if (t == T_STEPS - 1)
                g_hT[(bb * 4 + b) * HID + jb * 32 + rg] = h;
        }

        // ---- barrier: arrive (release DSMEM stores), prefetch next xp, wait ----
        CLUSTER_ARRIVE();
        {
            int tn = (t + 1 < T_STEPS) ? (t + 1) : (T_STEPS - 1);
            if (tid < 128)
                xp_pf = __ldg((const float4*)(xp_base + (size_t)tn * BATCH * (4 * HID)));
        }
        CLUSTER_WAIT();
        p ^= 1;
    }
}

// ---------- kernel 4: out[b] = h_T[b] @ W_out^T + b_out ----------
__global__ void __launch_bounds__(256) k_out(const float* __restrict__ Wout,
                                             const float* __restrict__ bout,
                                             float* __restrict__ out) {
    const int b = blockIdx.x;
    const int tid = threadIdx.x;
    float v = g_hT[b * HID + tid] * __ldg(Wout + tid);
#pragma unroll
    for (int d = 16; d >= 1; d >>= 1) v += __shfl_xor_sync(0xffffffffu, v, d);
    __shared__ float s[8];
    if ((tid & 31) == 0) s[tid >> 5] = v;
    __syncthreads();
    if (tid == 0) {
        float acc = 0.f;
#pragma unroll
        for (int i = 0; i < 8; ++i) acc += s[i];
        out[b] = acc + __ldg(bout);
    }
}

// ---------- launch ----------
extern "C" void kernel_launch(void* const* d_in, const int* in_sizes, int n_in,
                              void* d_out, int out_size) {
    const float* xd   = (const float*)d_in[0];
    const float* w    = (const float*)d_in[1];
    const float* Wih  = (const float*)d_in[2];
    const float* bih  = (const float*)d_in[3];
    const float* Whh  = (const float*)d_in[4];
    const float* bhh  = (const float*)d_in[5];
    const float* Wout = (const float*)d_in[6];
    const float* bout = (const float*)d_in[7];
    float* out = (float*)d_out;

    k_gate<<<(BATCH * T_STEPS * INDIM) / (256 * 4), 256>>>(xd, w);

    dim3 gx(1024 / 64, (BATCH * T_STEPS) / 128);
    k_xpart<<<gx, 256>>>(Wih, bih, bhh);

    k_rec<<<GJ * GB, 256>>>(Whh);   // 128 CTAs, 16 clusters of 8

    k_out<<<BATCH, 256>>>(Wout, bout, out);
}